// round 4
// baseline (speedup 1.0000x reference)
#include <cuda_runtime.h>
#include <cuda_bf16.h>

// Problem constants
#define BDIM 2048   // batch rows
#define SDIM 1024   // support vectors
#define FDIM 64     // features

// Tiling
#define BM 64       // rows per block = 32 lane pairs (r, r+32)
#define BN 32       // support cols per smem chunk
#define TN 8        // cols per warp (4 warps x 8 = 32 = BN)
#define NTHREADS 128
#define SSPLIT 16   // grid.y; each block covers 1024/16 = 64 S = 2 chunks

// Precomputed half-angle trig tables.
// X: pre-PAIRED per 64-row block: for f, blk, q:  rows r=blk*64+q, r+32
//    g_X4[f*1024 + blk*32 + q] = (cos r, cos r+32, sin r, sin r+32)
//    -> one lane-unique LDS.128 gives both packed f32x2 X operands.
// S: pre-SPLATTED: g_Sc2[f*1024 + j] = (cos j, cos j), g_Ss2 likewise
//    -> one broadcast LDS.128 gives 2 ready splatted columns.
__device__ float4 g_X4[FDIM * (BDIM / 2)];   // 1 MB
__device__ float2 g_Sc2[FDIM * SDIM];        // 512 KB
__device__ float2 g_Ss2[FDIM * SDIM];        // 512 KB

// ---- packed f32x2 helpers (ptxas will NOT auto-fuse; PTX only) --------------
#define MUL2(d, a, b) \
    asm("mul.rn.f32x2 %0, %1, %2;" : "=l"(d) : "l"(a), "l"(b))
#define FMA2(d, a, b, c) \
    asm("fma.rn.f32x2 %0, %1, %2, %3;" : "=l"(d) : "l"(a), "l"(b), "l"(c))
#define SPLAT2(d, x) \
    asm("mov.b64 %0, {%1, %1};" : "=l"(d) : "r"(__float_as_uint(x)))
#define UNPACK2(lo, hi, d) \
    asm("mov.b64 {%0, %1}, %2;" : "=r"(lo), "=r"(hi) : "l"(d))

typedef unsigned long long ull;

// ---------------------------------------------------------------------------
// Kernel A: precompute tables + initialize out[i] = b[0]
// ---------------------------------------------------------------------------
__global__ void precompute_kernel(const float* __restrict__ X,
                                  const float* __restrict__ S,
                                  const float* __restrict__ b,
                                  float* __restrict__ out) {
    int idx = blockIdx.x * blockDim.x + threadIdx.x;

    const int NX4 = FDIM * (BDIM / 2);   // 65536 float4 outputs
    const int NS  = FDIM * SDIM;         // 65536

    if (idx < NX4) {
        int f = idx >> 10;               // / 1024
        int e = idx & 1023;
        int blk = e >> 5;
        int q = e & 31;
        int r0 = blk * 64 + q;
        float v0 = X[r0 * FDIM + f];
        float v1 = X[(r0 + 32) * FDIM + f];
        float s0, c0, s1, c1;
        __sincosf(0.5f * v0, &s0, &c0);
        __sincosf(0.5f * v1, &s1, &c1);
        g_X4[idx] = make_float4(c0, c1, s0, s1);
    } else if (idx < NX4 + NS) {
        int e = idx - NX4;
        int f = e >> 10;
        int j = e & (SDIM - 1);
        float v = S[j * FDIM + f];
        float s, c;
        __sincosf(0.5f * v, &s, &c);
        g_Sc2[e] = make_float2(c, c);
        g_Ss2[e] = make_float2(s, s);
    }

    if (idx < BDIM) {
        out[idx] = b[0];                 // global atomics accumulate on top
    }
}

// ---------------------------------------------------------------------------
// Kernel B: grid (2048/64, 16), 128 threads (4 warps).
//   Lane owns row pair (rowbase+lane, rowbase+lane+32), packed in f32x2.
//   Warp w owns cols [w*8, w*8+8): S loads broadcast (1 wavefront each).
//   Inner loop: 1 LDS.128 (X) + 8 LDS.128 (S) + 24 packed f32x2 — no MOVs.
// ---------------------------------------------------------------------------
__global__ __launch_bounds__(NTHREADS)
void qkr_main_kernel(const float* __restrict__ W,
                     float* __restrict__ out) {
    extern __shared__ __align__(16) char dyn[];
    float4* sX4  = (float4*)dyn;                    // [64][32]  32 KB
    float2* sSc2 = (float2*)(dyn + 32768);          // [64][32]  16 KB
    float2* sSs2 = (float2*)(dyn + 49152);          // [64][32]  16 KB
    __shared__ float rowacc[BM];

    const int tid  = threadIdx.x;
    const int lane = tid & 31;
    const int warp = tid >> 5;          // 0..3
    const int col0 = warp * TN;         // 0,8,16,24

    // Fill X pair tile: 2048 float4, 16 per thread, fully coalesced
    #pragma unroll
    for (int e = tid; e < FDIM * 32; e += NTHREADS) {
        int f = e >> 5;
        int q = e & 31;
        sX4[e] = g_X4[f * (BDIM / 2) + blockIdx.x * 32 + q];
    }
    if (tid < BM) rowacc[tid] = 0.0f;

    ull acc2;
    SPLAT2(acc2, 0.0f);

    const int jsplit_base = blockIdx.y * (SDIM / SSPLIT);   // 64 S per block

    for (int chunk = 0; chunk < 2; chunk++) {
        const int jbase = jsplit_base + chunk * BN;

        __syncthreads();   // protect sS overwrite (covers sX fill on chunk 0)
        #pragma unroll
        for (int e = tid; e < FDIM * BN; e += NTHREADS) {   // 16 per thread
            int f = e >> 5;
            int c = e & (BN - 1);
            sSc2[e] = g_Sc2[f * SDIM + jbase + c];
            sSs2[e] = g_Ss2[f * SDIM + jbase + c];
        }
        __syncthreads();

        // p[c] = packed prod_f cos((x - s_c)/2) over the lane's row pair
        ull p[TN];
        #pragma unroll
        for (int c = 0; c < TN; c++) SPLAT2(p[c], 1.0f);

        #pragma unroll 4
        for (int f = 0; f < FDIM; f++) {
            // X: one lane-unique 128-bit load -> (xc pair, xs pair)
            ulonglong2 xv = *(const ulonglong2*)&sX4[f * 32 + lane];
            ull xc2 = xv.x;
            ull xs2 = xv.y;

            // S: broadcast 128-bit loads of pre-splatted pairs (2 cols each)
            const ulonglong2* scp = (const ulonglong2*)&sSc2[f * BN + col0];
            const ulonglong2* ssp = (const ulonglong2*)&sSs2[f * BN + col0];
            ulonglong2 a0 = scp[0], a1 = scp[1], a2 = scp[2], a3 = scp[3];
            ulonglong2 b0 = ssp[0], b1 = ssp[1], b2 = ssp[2], b3 = ssp[3];
            ull sc[TN] = { a0.x, a0.y, a1.x, a1.y, a2.x, a2.y, a3.x, a3.y };
            ull ss[TN] = { b0.x, b0.y, b1.x, b1.y, b2.x, b2.y, b3.x, b3.y };

            #pragma unroll
            for (int c = 0; c < TN; c++) {
                ull t;
                MUL2(t, xc2, sc[c]);        // xc*sc
                FMA2(t, xs2, ss[c], t);     // + xs*ss = cos((x-s)/2)
                MUL2(p[c], p[c], t);        // signed running product
            }
        }

        // epilogue: acc2 += W[j] * (prod cos)^2   (packed over the row pair)
        #pragma unroll
        for (int c = 0; c < TN; c++) {
            ull w2, sq;
            SPLAT2(w2, __ldg(&W[jbase + col0 + c]));
            MUL2(sq, p[c], p[c]);
            FMA2(acc2, sq, w2, acc2);
        }
    }

    // Block-level row reduction (4 warps per row), then one global atomic/row.
    unsigned int alo, ahi;
    UNPACK2(alo, ahi, acc2);
    atomicAdd(&rowacc[lane],      __uint_as_float(alo));
    atomicAdd(&rowacc[lane + 32], __uint_as_float(ahi));
    __syncthreads();
    if (tid < BM) {
        atomicAdd(&out[blockIdx.x * BM + tid], rowacc[tid]);
    }
}

// ---------------------------------------------------------------------------
extern "C" void kernel_launch(void* const* d_in, const int* in_sizes, int n_in,
                              void* d_out, int out_size) {
    const float* X = (const float*)d_in[0];   // [2048, 64]
    const float* S = (const float*)d_in[1];   // [1024, 64]
    const float* W = (const float*)d_in[2];   // [1, 1024]
    const float* b = (const float*)d_in[3];   // [1]
    float* out = (float*)d_out;               // [2048]

    {
        int total = FDIM * (BDIM / 2) + FDIM * SDIM;   // 131072
        int threads = 256;
        int blocks = (total + threads - 1) / threads;
        precompute_kernel<<<blocks, threads>>>(X, S, b, out);
    }
    {
        const int dyn_bytes = 65536;   // 32K X + 16K Sc + 16K Ss
        cudaFuncSetAttribute(qkr_main_kernel,
                             cudaFuncAttributeMaxDynamicSharedMemorySize,
                             dyn_bytes);
        dim3 grid(BDIM / BM, SSPLIT);   // (32, 16) = 512 blocks
        qkr_main_kernel<<<grid, NTHREADS, dyn_bytes>>>(W, out);
    }
}

// round 5
// speedup vs baseline: 1.7842x; 1.7842x over previous
#include <cuda_runtime.h>
#include <cuda_bf16.h>

// Problem constants
#define BDIM 2048   // batch rows
#define SDIM 1024   // support vectors
#define FDIM 64     // features

// Tiling
#define BM 64       // rows per block (warp lanes = 32 rows x 2 row-groups)
#define BN 32       // support cols per smem chunk
#define TN 8        // cols per warp (4 warps x 8 = 32 = BN)
#define NTHREADS 128
#define SSPLIT 16   // grid.y; each block covers 1024/16 = 64 S = 2 chunks

// Precomputed half-angle trig tables, SoA + transposed [f][elem]:
// coalesced smem fills, conflict-free lane-unique X loads, packed-pair S loads.
__device__ float g_Xc[FDIM * BDIM];
__device__ float g_Xs[FDIM * BDIM];
__device__ float g_Sc[FDIM * SDIM];
__device__ float g_Ss[FDIM * SDIM];

// ---- packed f32x2 helpers (ptxas will NOT auto-fuse; PTX only) --------------
#define MUL2(d, a, b) \
    asm("mul.rn.f32x2 %0, %1, %2;" : "=l"(d) : "l"(a), "l"(b))
#define FMA2(d, a, b, c) \
    asm("fma.rn.f32x2 %0, %1, %2, %3;" : "=l"(d) : "l"(a), "l"(b), "l"(c))
#define SPLAT2(d, x) \
    asm("mov.b64 %0, {%1, %1};" : "=l"(d) : "r"(__float_as_uint(x)))
#define UNPACK2(lo, hi, d) \
    asm("mov.b64 {%0, %1}, %2;" : "=r"(lo), "=r"(hi) : "l"(d))

typedef unsigned long long ull;

// ---------------------------------------------------------------------------
// Kernel A: precompute trig tables + initialize out[i] = b[0]
// ---------------------------------------------------------------------------
__global__ void precompute_kernel(const float* __restrict__ X,
                                  const float* __restrict__ S,
                                  const float* __restrict__ b,
                                  float* __restrict__ out) {
    int idx = blockIdx.x * blockDim.x + threadIdx.x;

    const int NX = FDIM * BDIM;     // 131072
    const int NS = FDIM * SDIM;     // 65536

    if (idx < NX) {
        int f = idx >> 11;          // / 2048
        int i = idx & (BDIM - 1);
        float v = X[i * FDIM + f];
        float s, c;
        __sincosf(0.5f * v, &s, &c);
        g_Xc[idx] = c;
        g_Xs[idx] = s;
    } else if (idx < NX + NS) {
        int e = idx - NX;
        int f = e >> 10;            // / 1024
        int j = e & (SDIM - 1);
        float v = S[j * FDIM + f];
        float s, c;
        __sincosf(0.5f * v, &s, &c);
        g_Sc[e] = c;
        g_Ss[e] = s;
    }

    if (idx < BDIM) {
        out[idx] = b[0];            // global atomics accumulate on top
    }
}

// ---------------------------------------------------------------------------
// Kernel B: grid (2048/64, 16), 128 threads (4 warps).
//   Warp lanes = 32 distinct rows (x2 row-groups: lane, lane+32)
//     -> X LDS.32 loads are lane-unique (no broadcast waste).
//   Warp w owns cols [w*8, w*8+8) of the BN=32 chunk
//     -> S LDS.128 loads are all-lanes-same-address (1 wavefront each).
//   Inner math in packed f32x2. X scalars software-prefetched one f ahead.
// ---------------------------------------------------------------------------
__global__ __launch_bounds__(NTHREADS)
void qkr_main_kernel(const float* __restrict__ W,
                     float* __restrict__ out) {
    __shared__ __align__(16) float sXc[FDIM][BM];   // 16 KB
    __shared__ __align__(16) float sXs[FDIM][BM];   // 16 KB
    __shared__ __align__(16) float sSc[FDIM][BN];   //  8 KB
    __shared__ __align__(16) float sSs[FDIM][BN];   //  8 KB
    __shared__ float rowacc[BM];

    const int tid  = threadIdx.x;
    const int lane = tid & 31;
    const int warp = tid >> 5;          // 0..3
    const int col0 = warp * TN;         // 0,8,16,24 (16B aligned in sS rows)
    const int rowbase = blockIdx.x * BM;

    // Fill X tiles: 2 x 4096 floats, 32 per thread, coalesced
    #pragma unroll
    for (int e = tid; e < FDIM * BM; e += NTHREADS) {
        int f = e >> 6;
        int r = e & (BM - 1);
        sXc[f][r] = g_Xc[f * BDIM + rowbase + r];
        sXs[f][r] = g_Xs[f * BDIM + rowbase + r];
    }
    if (tid < BM) rowacc[tid] = 0.0f;

    float acc0 = 0.0f, acc1 = 0.0f;     // row-group accumulators

    const int jsplit_base = blockIdx.y * (SDIM / SSPLIT);   // 64 S per block

    for (int chunk = 0; chunk < (SDIM / SSPLIT) / BN; chunk++) {   // 2 chunks
        const int jbase = jsplit_base + chunk * BN;

        __syncthreads();   // protect sS overwrite (covers sX fill on chunk 0)
        #pragma unroll
        for (int e = tid; e < FDIM * BN; e += NTHREADS) {          // 16/thread
            int f = e >> 5;
            int c = e & (BN - 1);
            sSc[f][c] = g_Sc[f * SDIM + jbase + c];
            sSs[f][c] = g_Ss[f * SDIM + jbase + c];
        }
        __syncthreads();

        // packed products: p[m][np] = prod_f cos((x - s)/2) for col pair np
        ull p[2][4];
        #pragma unroll
        for (int m = 0; m < 2; m++)
            #pragma unroll
            for (int np = 0; np < 4; np++)
                SPLAT2(p[m][np], 1.0f);

        // X prefetch registers (iteration f+1 loaded during iteration f)
        float nxc0 = sXc[0][lane], nxs0 = sXs[0][lane];
        float nxc1 = sXc[0][lane + 32], nxs1 = sXs[0][lane + 32];

        #pragma unroll 2
        for (int f = 0; f < FDIM; f++) {
            float cxc0 = nxc0, cxs0 = nxs0, cxc1 = nxc1, cxs1 = nxs1;
            if (f + 1 < FDIM) {
                nxc0 = sXc[f + 1][lane];
                nxs0 = sXs[f + 1][lane];
                nxc1 = sXc[f + 1][lane + 32];
                nxs1 = sXs[f + 1][lane + 32];
            }

            ull xc2[2], xs2[2];
            SPLAT2(xc2[0], cxc0);
            SPLAT2(xs2[0], cxs0);
            SPLAT2(xc2[1], cxc1);
            SPLAT2(xs2[1], cxs1);

            // S: broadcast 128-bit loads -> two packed pairs each
            ulonglong2 scA = *(const ulonglong2*)&sSc[f][col0];
            ulonglong2 scB = *(const ulonglong2*)&sSc[f][col0 + 4];
            ulonglong2 ssA = *(const ulonglong2*)&sSs[f][col0];
            ulonglong2 ssB = *(const ulonglong2*)&sSs[f][col0 + 4];
            ull sc[4] = { scA.x, scA.y, scB.x, scB.y };
            ull ss[4] = { ssA.x, ssA.y, ssB.x, ssB.y };

            #pragma unroll
            for (int m = 0; m < 2; m++) {
                #pragma unroll
                for (int np = 0; np < 4; np++) {
                    ull t;
                    MUL2(t, xc2[m], sc[np]);        // xc*sc
                    FMA2(t, xs2[m], ss[np], t);     // + xs*ss = cos((x-s)/2)
                    MUL2(p[m][np], p[m][np], t);    // signed running product
                }
            }
        }

        // epilogue: K = (prod cos)^2 ; acc += W[j] * K
        #pragma unroll
        for (int np = 0; np < 4; np++) {
            int jc = jbase + col0 + np * 2;
            float w0 = __ldg(&W[jc]);
            float w1 = __ldg(&W[jc + 1]);

            unsigned int a, b_;
            UNPACK2(a, b_, p[0][np]);
            float pa = __uint_as_float(a), pb = __uint_as_float(b_);
            acc0 = fmaf(w0, pa * pa, acc0);
            acc0 = fmaf(w1, pb * pb, acc0);

            UNPACK2(a, b_, p[1][np]);
            pa = __uint_as_float(a); pb = __uint_as_float(b_);
            acc1 = fmaf(w0, pa * pa, acc1);
            acc1 = fmaf(w1, pb * pb, acc1);
        }
    }

    // Block-level row reduction in shared (4 warps hit each row), then
    // one global atomic per row per block (32 blocks/row total).
    atomicAdd(&rowacc[lane], acc0);
    atomicAdd(&rowacc[lane + 32], acc1);
    __syncthreads();
    if (tid < BM) {
        atomicAdd(&out[rowbase + tid], rowacc[tid]);
    }
}

// ---------------------------------------------------------------------------
extern "C" void kernel_launch(void* const* d_in, const int* in_sizes, int n_in,
                              void* d_out, int out_size) {
    const float* X = (const float*)d_in[0];   // [2048, 64]
    const float* S = (const float*)d_in[1];   // [1024, 64]
    const float* W = (const float*)d_in[2];   // [1, 1024]
    const float* b = (const float*)d_in[3];   // [1]
    float* out = (float*)d_out;               // [2048]

    {
        int total = FDIM * BDIM + FDIM * SDIM;   // 196608
        int threads = 256;
        int blocks = (total + threads - 1) / threads;
        precompute_kernel<<<blocks, threads>>>(X, S, b, out);
    }
    {
        dim3 grid(BDIM / BM, SSPLIT);   // (32, 16) = 512 blocks
        qkr_main_kernel<<<grid, NTHREADS>>>(W, out);
    }
}

// round 6
// speedup vs baseline: 2.4157x; 1.3539x over previous
#include <cuda_runtime.h>
#include <cuda_bf16.h>

// Problem constants
#define BDIM 2048   // batch rows
#define SDIM 1024   // support vectors
#define FDIM 64     // features

// Tiling
#define BM 64       // rows per block = 32 lane-pairs (r, r+32)
#define BN 32       // support cols per block (one chunk)
#define TN 8        // cols per warp (4 warps x 8 = 32 = BN)
#define NTHREADS 128
#define SSPLIT 32   // grid.y; each block covers 1024/32 = 32 S = exactly 1 chunk

// Precomputed half-angle trig tables in bf16.
// X pre-PAIRED per 64-row block: for (f, blk, q), rows r = blk*64+q and r+32:
//   g_Xb[f*1024 + blk*32 + q] = { bf16x2(cos_r, cos_{r+32}), bf16x2(sin_r, sin_{r+32}) }
//   -> one lane-unique LDS.64 yields both packed X operands, no splat MOVs.
// S pre-SPLATTED: g_Scb[f*1024 + j] = bf16x2(cos_j, cos_j); g_Ssb likewise.
//   -> one broadcast LDS.128 yields 4 ready splatted columns.
__device__ uint2    g_Xb[FDIM * (BDIM / 2)];   // 512 KB
__device__ unsigned g_Scb[FDIM * SDIM];        // 256 KB
__device__ unsigned g_Ssb[FDIM * SDIM];        // 256 KB

static __device__ __forceinline__ __nv_bfloat162 u2bf2(unsigned u) {
    return *reinterpret_cast<__nv_bfloat162*>(&u);
}

// ---------------------------------------------------------------------------
// Kernel A: precompute bf16 trig tables + initialize out[i] = b[0]
// ---------------------------------------------------------------------------
__global__ void precompute_kernel(const float* __restrict__ X,
                                  const float* __restrict__ S,
                                  const float* __restrict__ b,
                                  float* __restrict__ out) {
    int idx = blockIdx.x * blockDim.x + threadIdx.x;

    const int NX2 = FDIM * (BDIM / 2);   // 65536 X pair entries
    const int NS  = FDIM * SDIM;         // 65536

    if (idx < NX2) {
        int f = idx >> 10;               // / 1024
        int e = idx & 1023;
        int blk = e >> 5;
        int q = e & 31;
        int r0 = blk * 64 + q;
        float v0 = X[r0 * FDIM + f];
        float v1 = X[(r0 + 32) * FDIM + f];
        float s0, c0, s1, c1;
        __sincosf(0.5f * v0, &s0, &c0);
        __sincosf(0.5f * v1, &s1, &c1);
        __nv_bfloat162 cp = __floats2bfloat162_rn(c0, c1);  // (lo=r, hi=r+32)
        __nv_bfloat162 sp = __floats2bfloat162_rn(s0, s1);
        g_Xb[idx] = make_uint2(*reinterpret_cast<unsigned*>(&cp),
                               *reinterpret_cast<unsigned*>(&sp));
    } else if (idx < NX2 + NS) {
        int e = idx - NX2;
        int f = e >> 10;
        int j = e & (SDIM - 1);
        float v = S[j * FDIM + f];
        float s, c;
        __sincosf(0.5f * v, &s, &c);
        __nv_bfloat162 cc = __floats2bfloat162_rn(c, c);
        __nv_bfloat162 ss = __floats2bfloat162_rn(s, s);
        g_Scb[e] = *reinterpret_cast<unsigned*>(&cc);
        g_Ssb[e] = *reinterpret_cast<unsigned*>(&ss);
    }

    if (idx < BDIM) {
        out[idx] = b[0];                 // global atomics accumulate on top
    }
}

// ---------------------------------------------------------------------------
// Kernel B: grid (2048/64, 32) = 1024 blocks, 128 threads (4 warps).
//   Lane owns row pair (rowbase+lane, rowbase+lane+32) packed in bf16x2.
//   Warp w owns cols [w*8, w*8+8): S loads are broadcast LDS.128 (1 wf each).
//   Inner iter: 1 LDS.64 (X) + 4 LDS.128 (S) + 24 bf16x2 ops. No MOVs.
//   Smem 32.3 KB -> ~7 blocks/SM; FMA pipe is the sole floor.
// ---------------------------------------------------------------------------
__global__ __launch_bounds__(NTHREADS)
void qkr_main_kernel(const float* __restrict__ W,
                     float* __restrict__ out) {
    __shared__ __align__(16) uint2    sX[FDIM * 32];     // 16 KB  [f*32 + q]
    __shared__ __align__(16) unsigned sSc[FDIM * BN];    //  8 KB  [f*32 + c]
    __shared__ __align__(16) unsigned sSs[FDIM * BN];    //  8 KB
    __shared__ float rowacc[BM];

    const int tid  = threadIdx.x;
    const int lane = tid & 31;
    const int warp = tid >> 5;          // 0..3
    const int col0 = warp * TN;         // 0,8,16,24 (uint4-aligned in sS rows)
    const int jbase = blockIdx.y * BN;  // 32 support cols for this block

    // Fills: 2048 elements each, 16 per thread, fully coalesced
    #pragma unroll
    for (int e = tid; e < FDIM * 32; e += NTHREADS) {
        int f = e >> 5;
        int q = e & 31;
        sX[e] = g_Xb[f * (BDIM / 2) + blockIdx.x * 32 + q];
    }
    #pragma unroll
    for (int e = tid; e < FDIM * BN; e += NTHREADS) {
        int f = e >> 5;
        int c = e & (BN - 1);
        sSc[e] = g_Scb[f * SDIM + jbase + c];
        sSs[e] = g_Ssb[f * SDIM + jbase + c];
    }
    if (tid < BM) rowacc[tid] = 0.0f;
    __syncthreads();

    // p[c] = bf16x2 running product of cos((x - s_c)/2) over the lane's row pair
    __nv_bfloat162 p[TN];
    const __nv_bfloat162 one2 = __float2bfloat162_rn(1.0f);
    #pragma unroll
    for (int c = 0; c < TN; c++) p[c] = one2;

    #pragma unroll 4
    for (int f = 0; f < FDIM; f++) {
        uint2 xv = sX[f * 32 + lane];                    // lane-unique LDS.64
        __nv_bfloat162 xc = u2bf2(xv.x);
        __nv_bfloat162 xs = u2bf2(xv.y);

        // broadcast LDS.128: 4 splatted cols each
        uint4 ca = *(const uint4*)&sSc[f * BN + col0];
        uint4 cb = *(const uint4*)&sSc[f * BN + col0 + 4];
        uint4 sa = *(const uint4*)&sSs[f * BN + col0];
        uint4 sb = *(const uint4*)&sSs[f * BN + col0 + 4];
        unsigned scu[TN] = { ca.x, ca.y, ca.z, ca.w, cb.x, cb.y, cb.z, cb.w };
        unsigned ssu[TN] = { sa.x, sa.y, sa.z, sa.w, sb.x, sb.y, sb.z, sb.w };

        #pragma unroll
        for (int c = 0; c < TN; c++) {
            __nv_bfloat162 t = __hmul2(xc, u2bf2(scu[c]));   // xc*sc
            t = __hfma2(xs, u2bf2(ssu[c]), t);               // + xs*ss
            p[c] = __hmul2(p[c], t);                         // running product
        }
    }

    // Epilogue in f32: K = (prod cos)^2 ; acc += W[j] * K
    float acc0 = 0.0f, acc1 = 0.0f;
    #pragma unroll
    for (int c = 0; c < TN; c++) {
        float w  = __ldg(&W[jbase + col0 + c]);
        float lo = __low2float(p[c]);
        float hi = __high2float(p[c]);
        acc0 = fmaf(w, lo * lo, acc0);
        acc1 = fmaf(w, hi * hi, acc1);
    }

    // Block-level row reduction (4 warps per row), then 1 global atomic/row.
    atomicAdd(&rowacc[lane],      acc0);
    atomicAdd(&rowacc[lane + 32], acc1);
    __syncthreads();
    if (tid < BM) {
        atomicAdd(&out[blockIdx.x * BM + tid], rowacc[tid]);
    }
}

// ---------------------------------------------------------------------------
extern "C" void kernel_launch(void* const* d_in, const int* in_sizes, int n_in,
                              void* d_out, int out_size) {
    const float* X = (const float*)d_in[0];   // [2048, 64]
    const float* S = (const float*)d_in[1];   // [1024, 64]
    const float* W = (const float*)d_in[2];   // [1, 1024]
    const float* b = (const float*)d_in[3];   // [1]
    float* out = (float*)d_out;               // [2048]

    {
        int total = FDIM * (BDIM / 2) + FDIM * SDIM;   // 131072
        int threads = 256;
        int blocks = (total + threads - 1) / threads;
        precompute_kernel<<<blocks, threads>>>(X, S, b, out);
    }
    {
        dim3 grid(BDIM / BM, SSPLIT);   // (32, 32) = 1024 blocks
        qkr_main_kernel<<<grid, NTHREADS>>>(W, out);
    }
}